// round 2
// baseline (speedup 1.0000x reference)
#include <cuda_runtime.h>
#include <math.h>

#define Bb 256
#define Tt 128
#define Vv 512
#define Ee 64
#define Hh 256
#define G4 1024
#define KD 320
#define NB 128
#define NT 256

// ---------------- device scratch (static allocation is allowed) ----------------
__device__ float g_Gx[(size_t)Bb * Tt * G4];   // encoder input gates, packed cols, bias folded
__device__ float g_Xe[(size_t)Bb * Tt * Ee];
__device__ float g_WeT[Vv * Ee];
__device__ float g_WihTpE[Ee * G4];
__device__ float g_WhhTpE[Hh * G4];
__device__ float g_biasE[G4];
__device__ float g_WsTpD[KD * G4];             // [emb|h] stacked, packed cols
__device__ float g_biasD[G4];
__device__ float g_WoT[Hh * Vv];
__device__ float g_WdT[Vv * Ee];
__device__ float g_h[2][Bb * Hh];
__device__ float g_emb[Bb * Ee];
__device__ unsigned g_cnt = 0;
__device__ unsigned g_gen = 0;

// ---------------- helpers ----------------
__device__ __forceinline__ float ldcg(const float* p) {
    float v; asm volatile("ld.global.cg.f32 %0, [%1];" : "=f"(v) : "l"(p)); return v;
}
__device__ __forceinline__ void stcg(float* p, float v) {
    asm volatile("st.global.cg.f32 [%0], %1;" :: "l"(p), "f"(v));
}
__device__ __forceinline__ float sigm(float x) { return 1.0f / (1.0f + expf(-x)); }

__device__ __forceinline__ void grid_bar() {
    __threadfence();
    __syncthreads();
    if (threadIdx.x == 0) {
        unsigned gen = *((volatile unsigned*)&g_gen);
        __threadfence();
        if (atomicAdd(&g_cnt, 1u) == (unsigned)(NB - 1)) {
            g_cnt = 0;
            __threadfence();
            atomicExch(&g_gen, gen + 1u);
        } else {
            while (*((volatile unsigned*)&g_gen) == gen) { __nanosleep(40); }
        }
    }
    __syncthreads();
}

// ---------------- pack weights (transpose + gate-interleave) ----------------
// packed col p: q = p&3 (i,f,g,o), j = p>>2 ; orig gate row = q*H + j
__global__ void pack_kernel(const float* __restrict__ We,
                            const float* __restrict__ Wih_e, const float* __restrict__ Whh_e,
                            const float* __restrict__ bih_e, const float* __restrict__ bhh_e,
                            const float* __restrict__ Wd,
                            const float* __restrict__ Wih_d, const float* __restrict__ Whh_d,
                            const float* __restrict__ bih_d, const float* __restrict__ bhh_d,
                            const float* __restrict__ Wo) {
    const int R0 = Hh * G4;         // WhhTpE
    const int R1 = R0 + Ee * G4;    // WihTpE
    const int R2 = R1 + KD * G4;    // WsTpD
    const int R3 = R2 + Hh * Vv;    // WoT
    const int R4 = R3 + Vv * Ee;    // WdT
    const int R5 = R4 + Vv * Ee;    // WeT
    const int R6 = R5 + G4;         // biasE
    const int R7 = R6 + G4;         // biasD
    for (int id = blockIdx.x * blockDim.x + threadIdx.x; id < R7; id += gridDim.x * blockDim.x) {
        if (id < R0) {
            int k = id / G4, p = id % G4, q = p & 3, j = p >> 2;
            g_WhhTpE[id] = Whh_e[(q * Hh + j) * Hh + k];
        } else if (id < R1) {
            int t = id - R0; int e = t / G4, p = t % G4, q = p & 3, j = p >> 2;
            g_WihTpE[t] = Wih_e[(q * Hh + j) * Ee + e];
        } else if (id < R2) {
            int t = id - R1; int k = t / G4, p = t % G4, q = p & 3, j = p >> 2;
            g_WsTpD[t] = (k < Ee) ? Wih_d[(q * Hh + j) * Ee + k]
                                  : Whh_d[(q * Hh + j) * Hh + (k - Ee)];
        } else if (id < R3) {
            int t = id - R2; int k = t / Vv, v = t % Vv;
            g_WoT[t] = Wo[v * Hh + k];
        } else if (id < R4) {
            int t = id - R3; int v = t / Ee, e = t % Ee;
            g_WdT[t] = Wd[e * Vv + v];
        } else if (id < R5) {
            int t = id - R4; int v = t / Ee, e = t % Ee;
            g_WeT[t] = We[e * Vv + v];
        } else if (id < R6) {
            int p = id - R5, q = p & 3, j = p >> 2;
            g_biasE[p] = bih_e[q * Hh + j] + bhh_e[q * Hh + j];
        } else {
            int p = id - R6, q = p & 3, j = p >> 2;
            g_biasD[p] = bih_d[q * Hh + j] + bhh_d[q * Hh + j];
        }
    }
}

// ---------------- Xe = x @ We^T + be  (M=32768, N=64, K=512) ----------------
__global__ void __launch_bounds__(256) xe_kernel(const float* __restrict__ x,
                                                 const float* __restrict__ be) {
    __shared__ float As[32][65];
    __shared__ float Bs[32][64];
    int tid = threadIdx.x;
    int tx = tid & 15, ty = tid >> 4;
    int m0 = blockIdx.x * 64;
    float acc[4][4];
#pragma unroll
    for (int c = 0; c < 4; c++) {
        float b = be[tx * 4 + c];
#pragma unroll
        for (int r = 0; r < 4; r++) acc[r][c] = b;
    }
    for (int kt = 0; kt < 16; ++kt) {
        int k0 = kt * 32;
        {
            int kk = tid & 31, mm = tid >> 5;
#pragma unroll
            for (int p = 0; p < 8; p++) {
                int m = mm + p * 8;
                As[kk][m] = x[(size_t)(m0 + m) * Vv + k0 + kk];
            }
        }
        {
            int ee = tid & 63, kk = tid >> 6;
#pragma unroll
            for (int p = 0; p < 8; p++) {
                int k = kk + p * 4;
                Bs[k][ee] = g_WeT[(size_t)(k0 + k) * Ee + ee];
            }
        }
        __syncthreads();
#pragma unroll
        for (int kk = 0; kk < 32; kk++) {
            float a[4], b[4];
#pragma unroll
            for (int r = 0; r < 4; r++) a[r] = As[kk][ty * 4 + r];
#pragma unroll
            for (int c = 0; c < 4; c++) b[c] = Bs[kk][tx * 4 + c];
#pragma unroll
            for (int r = 0; r < 4; r++)
#pragma unroll
                for (int c = 0; c < 4; c++) acc[r][c] += a[r] * b[c];
        }
        __syncthreads();
    }
#pragma unroll
    for (int r = 0; r < 4; r++) {
        int m = m0 + ty * 4 + r;
#pragma unroll
        for (int c = 0; c < 4; c++) g_Xe[(size_t)m * Ee + tx * 4 + c] = acc[r][c];
    }
}

// ---------------- Gx = Xe @ WihTpE + biasE  (M=32768, N=1024, K=64) ----------------
__global__ void __launch_bounds__(256) gx_kernel() {
    __shared__ float As[64][65];
    __shared__ float Bs[64][64];
    int tid = threadIdx.x;
    int tx = tid & 15, ty = tid >> 4;
    int m0 = blockIdx.x * 64;
    int n0 = blockIdx.y * 64;
    {
        int kk = tid & 63, mm = tid >> 6;
#pragma unroll
        for (int p = 0; p < 16; p++) {
            int m = mm + p * 4;
            As[kk][m] = g_Xe[(size_t)(m0 + m) * Ee + kk];
        }
    }
    {
        int nn = tid & 63, kk = tid >> 6;
#pragma unroll
        for (int p = 0; p < 16; p++) {
            int k = kk + p * 4;
            Bs[k][nn] = g_WihTpE[(size_t)k * G4 + n0 + nn];
        }
    }
    __syncthreads();
    float acc[4][4];
#pragma unroll
    for (int c = 0; c < 4; c++) {
        float b = g_biasE[n0 + tx * 4 + c];
#pragma unroll
        for (int r = 0; r < 4; r++) acc[r][c] = b;
    }
#pragma unroll
    for (int kk = 0; kk < 64; kk++) {
        float a[4], b[4];
#pragma unroll
        for (int r = 0; r < 4; r++) a[r] = As[kk][ty * 4 + r];
#pragma unroll
        for (int c = 0; c < 4; c++) b[c] = Bs[kk][tx * 4 + c];
#pragma unroll
        for (int r = 0; r < 4; r++)
#pragma unroll
            for (int c = 0; c < 4; c++) acc[r][c] += a[r] * b[c];
    }
#pragma unroll
    for (int r = 0; r < 4; r++) {
        int bt = m0 + ty * 4 + r;
        int b = bt >> 7, t = bt & 127;
        size_t base = ((size_t)t * Bb + b) * G4 + n0 + tx * 4;
#pragma unroll
        for (int c = 0; c < 4; c++) g_Gx[base + c] = acc[r][c];
    }
}

// ---------------- emb0 = x[:,0,:] @ Wd^T + bd ----------------
__global__ void emb0_kernel(const float* __restrict__ x, const float* __restrict__ bd) {
    __shared__ float x0[Vv];
    int b = blockIdx.x, tid = threadIdx.x; // 64 threads
    for (int i = tid; i < Vv; i += 64) x0[i] = x[(size_t)b * Tt * Vv + i];
    __syncthreads();
    float acc = bd[tid];
    for (int v = 0; v < Vv; v++) acc += x0[v] * g_WdT[(size_t)v * Ee + tid];
    g_emb[b * Ee + tid] = acc;
}

// ---------------- init: y[:,0,:]=0, x_lens -> out, h0=0 ----------------
__global__ void init_kernel(const int* __restrict__ xlens, float* __restrict__ out,
                            int write_extra) {
    int id = blockIdx.x * blockDim.x + threadIdx.x; // 131072 threads
    if (id < Bb * Vv) {
        int b = id / Vv, v = id % Vv;
        out[(size_t)b * Tt * Vv + v] = 0.f;
    }
    if (write_extra && id < Bb) out[(size_t)Bb * Tt * Vv + id] = (float)xlens[id];
    if (id < Bb * Hh) { g_h[0][id] = 0.f; g_h[1][id] = 0.f; }
}

// ---------------- persistent recurrent kernel ----------------
__global__ void __launch_bounds__(NT, 1) rec_kernel(const int* __restrict__ xlens,
                                                    const float* __restrict__ bd,
                                                    const float* __restrict__ bo,
                                                    float* __restrict__ out,
                                                    int write_extra) {
    __shared__ union {
        struct { float As[16][65]; float Bs[16][32]; } p1;
        struct { float hs[4][257]; float Ws[8][513]; float sv[4][256]; int si[4][256]; } p2;
    } sm;

    const int tid = threadIdx.x, bx = blockIdx.x;
    const int tx = tid & 15, ty = tid >> 4;
    const int m0 = (bx >> 5) * 64;       // 4 row tiles of 64
    const int n0 = (bx & 31) * 32;       // 32 col tiles of 32
    const int row0 = m0 + ty * 4;
    const int col0 = n0 + tx * 2;
    const bool evenT = ((tx & 1) == 0);
    const int junit = col0 >> 2;         // hidden unit owned when evenT

    float c_reg[4] = {0.f, 0.f, 0.f, 0.f};
    float h_reg[4] = {0.f, 0.f, 0.f, 0.f};
    int lens[4];
#pragma unroll
    for (int r = 0; r < 4; r++) lens[r] = xlens[row0 + r];

    int par = 0;
    const unsigned FULL = 0xffffffffu;

    // ======================= encoder: T steps =======================
    for (int t = 0; t < Tt; ++t) {
        float acc[4][2];
        const float* gx = g_Gx + ((size_t)t * Bb) * G4;
#pragma unroll
        for (int r = 0; r < 4; r++) {
            acc[r][0] = gx[(size_t)(row0 + r) * G4 + col0];
            acc[r][1] = gx[(size_t)(row0 + r) * G4 + col0 + 1];
        }
        const float* hbuf = g_h[par];
        for (int kt = 0; kt < Hh / 16; ++kt) {
            int k0 = kt * 16;
            {
                int kk = tid & 15, mm = tid >> 4;
#pragma unroll
                for (int p = 0; p < 4; p++) {
                    int m = mm + p * 16;
                    sm.p1.As[kk][m] = ldcg(&hbuf[(size_t)(m0 + m) * Hh + k0 + kk]);
                }
            }
            {
                int nn = tid & 31, kk = tid >> 5;
#pragma unroll
                for (int p = 0; p < 2; p++) {
                    int k = kk + p * 8;
                    sm.p1.Bs[k][nn] = g_WhhTpE[(size_t)(k0 + k) * G4 + n0 + nn];
                }
            }
            __syncthreads();
#pragma unroll
            for (int kk = 0; kk < 16; kk++) {
                float b0 = sm.p1.Bs[kk][tx * 2], b1 = sm.p1.Bs[kk][tx * 2 + 1];
#pragma unroll
                for (int r = 0; r < 4; r++) {
                    float a = sm.p1.As[kk][ty * 4 + r];
                    acc[r][0] += a * b0; acc[r][1] += a * b1;
                }
            }
            __syncthreads();
        }
        // cell (packed cols: even thread has i,f; odd has g,o)
#pragma unroll
        for (int r = 0; r < 4; r++) {
            float gg = __shfl_down_sync(FULL, acc[r][0], 1);
            float go = __shfl_down_sync(FULL, acc[r][1], 1);
            if (evenT) {
                float i_ = sigm(acc[r][0]), f_ = sigm(acc[r][1]);
                float gv = tanhf(gg), o_ = sigm(go);
                float cn = f_ * c_reg[r] + i_ * gv;
                float hn = o_ * tanhf(cn);
                bool msk = (t < lens[r]);
                c_reg[r] = msk ? cn : c_reg[r];
                float hv = msk ? hn : h_reg[r];
                h_reg[r] = hv;
                stcg(&g_h[par ^ 1][(size_t)(row0 + r) * Hh + junit], hv);
            }
        }
        grid_bar();
        par ^= 1;
    }

    // encoded = h_enc
    if (write_extra && evenT) {
#pragma unroll
        for (int r = 0; r < 4; r++)
            out[(size_t)Bb * Tt * Vv + Bb + (size_t)(row0 + r) * Hh + junit] = h_reg[r];
    }

    // ======================= decoder: T-1 steps =======================
    for (int s = 0; s < Tt - 1; ++s) {
        float acc[4][2];
        {
            float b0 = g_biasD[col0], b1 = g_biasD[col0 + 1];
#pragma unroll
            for (int r = 0; r < 4; r++) { acc[r][0] = b0; acc[r][1] = b1; }
        }
        const float* hbuf = g_h[par];
        for (int kt = 0; kt < KD / 16; ++kt) {
            int k0 = kt * 16;
            {
                int kk = tid & 15, mm = tid >> 4;
#pragma unroll
                for (int p = 0; p < 4; p++) {
                    int m = mm + p * 16;
                    int gk = k0 + kk;
                    float v;
                    if (gk < Ee) v = ldcg(&g_emb[(size_t)(m0 + m) * Ee + gk]);
                    else         v = ldcg(&hbuf[(size_t)(m0 + m) * Hh + gk - Ee]);
                    sm.p1.As[kk][m] = v;
                }
            }
            {
                int nn = tid & 31, kk = tid >> 5;
#pragma unroll
                for (int p = 0; p < 2; p++) {
                    int k = kk + p * 8;
                    sm.p1.Bs[k][nn] = g_WsTpD[(size_t)(k0 + k) * G4 + n0 + nn];
                }
            }
            __syncthreads();
#pragma unroll
            for (int kk = 0; kk < 16; kk++) {
                float b0 = sm.p1.Bs[kk][tx * 2], b1 = sm.p1.Bs[kk][tx * 2 + 1];
#pragma unroll
                for (int r = 0; r < 4; r++) {
                    float a = sm.p1.As[kk][ty * 4 + r];
                    acc[r][0] += a * b0; acc[r][1] += a * b1;
                }
            }
            __syncthreads();
        }
#pragma unroll
        for (int r = 0; r < 4; r++) {
            float gg = __shfl_down_sync(FULL, acc[r][0], 1);
            float go = __shfl_down_sync(FULL, acc[r][1], 1);
            if (evenT) {
                float i_ = sigm(acc[r][0]), f_ = sigm(acc[r][1]);
                float gv = tanhf(gg), o_ = sigm(go);
                float cn = f_ * c_reg[r] + i_ * gv;
                float hn = o_ * tanhf(cn);
                c_reg[r] = cn;
                h_reg[r] = hn;
                stcg(&g_h[par ^ 1][(size_t)(row0 + r) * Hh + junit], hn);
            }
        }
        grid_bar();
        par ^= 1;

        // ---- phase2: logits (256x512,K=256) + argmax + emb gather (blocks 0..63) ----
        if (bx < 64) {
            int r0 = bx * 4;
            const float* hbuf2 = g_h[par];
#pragma unroll
            for (int r = 0; r < 4; r++)
                sm.p2.hs[r][tid] = ldcg(&hbuf2[(size_t)(r0 + r) * Hh + tid]);
            float acc2[4][2];
            {
                float b0 = bo[tid], b1 = bo[tid + 256];
#pragma unroll
                for (int r = 0; r < 4; r++) { acc2[r][0] = b0; acc2[r][1] = b1; }
            }
            for (int kt = 0; kt < 32; ++kt) {
                __syncthreads();
#pragma unroll
                for (int kk = 0; kk < 8; kk++) {
                    sm.p2.Ws[kk][tid]       = g_WoT[(size_t)(kt * 8 + kk) * Vv + tid];
                    sm.p2.Ws[kk][tid + 256] = g_WoT[(size_t)(kt * 8 + kk) * Vv + tid + 256];
                }
                __syncthreads();
#pragma unroll
                for (int kk = 0; kk < 8; kk++) {
                    float w0 = sm.p2.Ws[kk][tid], w1 = sm.p2.Ws[kk][tid + 256];
#pragma unroll
                    for (int r = 0; r < 4; r++) {
                        float a = sm.p2.hs[r][kt * 8 + kk];
                        acc2[r][0] += a * w0; acc2[r][1] += a * w1;
                    }
                }
            }
            __syncthreads();
            // write y[:, s+1, :] and local argmax
#pragma unroll
            for (int r = 0; r < 4; r++) {
                size_t yb = (size_t)(r0 + r) * Tt * Vv + (size_t)(s + 1) * Vv;
                out[yb + tid]       = acc2[r][0];
                out[yb + tid + 256] = acc2[r][1];
                float bv = acc2[r][0]; int bi = tid;
                if (acc2[r][1] > bv) { bv = acc2[r][1]; bi = tid + 256; }
                sm.p2.sv[r][tid] = bv; sm.p2.si[r][tid] = bi;
            }
            __syncthreads();
            for (int st = 128; st > 0; st >>= 1) {
                if (tid < st) {
#pragma unroll
                    for (int r = 0; r < 4; r++) {
                        float v2 = sm.p2.sv[r][tid + st]; int i2 = sm.p2.si[r][tid + st];
                        float v1 = sm.p2.sv[r][tid];      int i1 = sm.p2.si[r][tid];
                        if (v2 > v1 || (v2 == v1 && i2 < i1)) {
                            sm.p2.sv[r][tid] = v2; sm.p2.si[r][tid] = i2;
                        }
                    }
                }
                __syncthreads();
            }
            // gather next emb: emb[b][e] = WdT[idx][e] + bd[e]
            {
                int r = tid >> 6, e = tid & 63;
                int idx = sm.p2.si[r][0];
                float ev = g_WdT[(size_t)idx * Ee + e] + bd[e];
                stcg(&g_emb[(size_t)(r0 + r) * Ee + e], ev);
            }
        }
        grid_bar();
    }
}

// ---------------- launch ----------------
extern "C" void kernel_launch(void* const* d_in, const int* in_sizes, int n_in,
                              void* d_out, int out_size) {
    (void)in_sizes; (void)n_in;
    const float* x     = (const float*)d_in[0];
    const int*   xlens = (const int*)  d_in[1];
    const float* We    = (const float*)d_in[2];
    const float* be    = (const float*)d_in[3];
    const float* Wih_e = (const float*)d_in[4];
    const float* Whh_e = (const float*)d_in[5];
    const float* bih_e = (const float*)d_in[6];
    const float* bhh_e = (const float*)d_in[7];
    const float* Wd    = (const float*)d_in[8];
    const float* bd    = (const float*)d_in[9];
    const float* Wih_d = (const float*)d_in[10];
    const float* Whh_d = (const float*)d_in[11];
    const float* bih_d = (const float*)d_in[12];
    const float* bhh_d = (const float*)d_in[13];
    const float* Wo    = (const float*)d_in[14];
    const float* bo    = (const float*)d_in[15];
    float* out = (float*)d_out;

    int write_extra = (out_size >= Bb * Tt * Vv + Bb + Bb * Hh) ? 1 : 0;

    pack_kernel<<<1024, 256>>>(We, Wih_e, Whh_e, bih_e, bhh_e,
                               Wd, Wih_d, Whh_d, bih_d, bhh_d, Wo);
    xe_kernel<<<512, 256>>>(x, be);
    gx_kernel<<<dim3(512, 16), 256>>>();
    emb0_kernel<<<Bb, 64>>>(x, bd);
    init_kernel<<<512, 256>>>(xlens, out, write_extra);
    rec_kernel<<<NB, NT>>>(xlens, bd, bo, out, write_extra);
}

// round 3
// speedup vs baseline: 1.4101x; 1.4101x over previous
#include <cuda_runtime.h>
#include <math.h>

#define Bb 256
#define Tt 128
#define Vv 512
#define Ee 64
#define Hh 256
#define G4 1024
#define KD 320
#define NB 128
#define NT 256

#define KT 32
#define NKT_E 8
#define NKT_D 10

// shared layout (floats)
#define WS_STRIDE 34
#define WS_FLOATS (KD * WS_STRIDE)          // 10880
#define AS_STRIDE 66
#define AS_BUF (KT * AS_STRIDE)             // 2112
#define AS_FLOATS (2 * AS_BUF)              // 4224
#define SIDX_OFF (WS_FLOATS + AS_FLOATS)    // 15104
#define DSM_FLOATS (SIDX_OFF + 64)          // 15168
#define DSM_BYTES (DSM_FLOATS * 4)

// ---------------- device scratch ----------------
__device__ float g_Gx[(size_t)Bb * Tt * G4];
__device__ float g_Xe[(size_t)Bb * Tt * Ee];
__device__ float g_WeT[Vv * Ee];
__device__ float g_WihTpE[Ee * G4];
__device__ float g_WhhTpE[Hh * G4];
__device__ float g_biasE[G4];
__device__ float g_WsTpD[KD * G4];
__device__ float g_biasD[G4];
__device__ float g_WoT[Hh * Vv];
__device__ float g_WdT[Vv * Ee];
__device__ float g_WdTb[Vv * Ee];
__device__ float g_h[2][Bb * Hh];
__device__ float g_emb[Bb * Ee];
__device__ float g_av[2 * Bb];
__device__ int   g_ai[2 * Bb];
__device__ unsigned g_cnt = 0;
__device__ unsigned g_gen = 0;

// ---------------- helpers ----------------
__device__ __forceinline__ float ldcg(const float* p) {
    float v; asm volatile("ld.global.cg.f32 %0, [%1];" : "=f"(v) : "l"(p)); return v;
}
__device__ __forceinline__ int ldcg_i(const int* p) {
    int v; asm volatile("ld.global.cg.s32 %0, [%1];" : "=r"(v) : "l"(p)); return v;
}
__device__ __forceinline__ void stcg(float* p, float v) {
    asm volatile("st.global.cg.f32 [%0], %1;" :: "l"(p), "f"(v));
}
__device__ __forceinline__ void stcg_i(int* p, int v) {
    asm volatile("st.global.cg.s32 [%0], %1;" :: "l"(p), "r"(v));
}
__device__ __forceinline__ float sigm(float x) { return 1.0f / (1.0f + expf(-x)); }

__device__ __forceinline__ void grid_bar() {
    __threadfence();
    __syncthreads();
    if (threadIdx.x == 0) {
        unsigned gen = *((volatile unsigned*)&g_gen);
        __threadfence();
        if (atomicAdd(&g_cnt, 1u) == (unsigned)(NB - 1)) {
            g_cnt = 0;
            __threadfence();
            atomicExch(&g_gen, gen + 1u);
        } else {
            while (*((volatile unsigned*)&g_gen) == gen) { __nanosleep(40); }
        }
    }
    __syncthreads();
}

// ---------------- pack weights ----------------
__global__ void pack_kernel(const float* __restrict__ We,
                            const float* __restrict__ Wih_e, const float* __restrict__ Whh_e,
                            const float* __restrict__ bih_e, const float* __restrict__ bhh_e,
                            const float* __restrict__ Wd, const float* __restrict__ bd,
                            const float* __restrict__ Wih_d, const float* __restrict__ Whh_d,
                            const float* __restrict__ bih_d, const float* __restrict__ bhh_d,
                            const float* __restrict__ Wo) {
    const int R0 = Hh * G4;
    const int R1 = R0 + Ee * G4;
    const int R2 = R1 + KD * G4;
    const int R3 = R2 + Hh * Vv;
    const int R4 = R3 + Vv * Ee;
    const int R5 = R4 + Vv * Ee;   // WdTb
    const int R6 = R5 + Vv * Ee;   // WeT
    const int R7 = R6 + G4;
    const int R8 = R7 + G4;
    for (int id = blockIdx.x * blockDim.x + threadIdx.x; id < R8; id += gridDim.x * blockDim.x) {
        if (id < R0) {
            int k = id / G4, p = id % G4, q = p & 3, j = p >> 2;
            g_WhhTpE[id] = Whh_e[(q * Hh + j) * Hh + k];
        } else if (id < R1) {
            int t = id - R0; int e = t / G4, p = t % G4, q = p & 3, j = p >> 2;
            g_WihTpE[t] = Wih_e[(q * Hh + j) * Ee + e];
        } else if (id < R2) {
            int t = id - R1; int k = t / G4, p = t % G4, q = p & 3, j = p >> 2;
            g_WsTpD[t] = (k < Ee) ? Wih_d[(q * Hh + j) * Ee + k]
                                  : Whh_d[(q * Hh + j) * Hh + (k - Ee)];
        } else if (id < R3) {
            int t = id - R2; int k = t / Vv, v = t % Vv;
            g_WoT[t] = Wo[v * Hh + k];
        } else if (id < R4) {
            int t = id - R3; int v = t / Ee, e = t % Ee;
            g_WdT[t] = Wd[e * Vv + v];
        } else if (id < R5) {
            int t = id - R4; int v = t / Ee, e = t % Ee;
            g_WdTb[t] = Wd[e * Vv + v] + bd[e];
        } else if (id < R6) {
            int t = id - R5; int v = t / Ee, e = t % Ee;
            g_WeT[t] = We[e * Vv + v];
        } else if (id < R7) {
            int p = id - R6, q = p & 3, j = p >> 2;
            g_biasE[p] = bih_e[q * Hh + j] + bhh_e[q * Hh + j];
        } else {
            int p = id - R7, q = p & 3, j = p >> 2;
            g_biasD[p] = bih_d[q * Hh + j] + bhh_d[q * Hh + j];
        }
    }
}

// ---------------- Xe = x @ We^T + be ----------------
__global__ void __launch_bounds__(256) xe_kernel(const float* __restrict__ x,
                                                 const float* __restrict__ be) {
    __shared__ float As[32][65];
    __shared__ float Bs[32][64];
    int tid = threadIdx.x;
    int tx = tid & 15, ty = tid >> 4;
    int m0 = blockIdx.x * 64;
    float acc[4][4];
#pragma unroll
    for (int c = 0; c < 4; c++) {
        float b = be[tx * 4 + c];
#pragma unroll
        for (int r = 0; r < 4; r++) acc[r][c] = b;
    }
    for (int kt = 0; kt < 16; ++kt) {
        int k0 = kt * 32;
        {
            int kk = tid & 31, mm = tid >> 5;
#pragma unroll
            for (int p = 0; p < 8; p++) {
                int m = mm + p * 8;
                As[kk][m] = x[(size_t)(m0 + m) * Vv + k0 + kk];
            }
        }
        {
            int ee = tid & 63, kk = tid >> 6;
#pragma unroll
            for (int p = 0; p < 8; p++) {
                int k = kk + p * 4;
                Bs[k][ee] = g_WeT[(size_t)(k0 + k) * Ee + ee];
            }
        }
        __syncthreads();
#pragma unroll
        for (int kk = 0; kk < 32; kk++) {
            float a[4], b[4];
#pragma unroll
            for (int r = 0; r < 4; r++) a[r] = As[kk][ty * 4 + r];
#pragma unroll
            for (int c = 0; c < 4; c++) b[c] = Bs[kk][tx * 4 + c];
#pragma unroll
            for (int r = 0; r < 4; r++)
#pragma unroll
                for (int c = 0; c < 4; c++) acc[r][c] += a[r] * b[c];
        }
        __syncthreads();
    }
#pragma unroll
    for (int r = 0; r < 4; r++) {
        int m = m0 + ty * 4 + r;
#pragma unroll
        for (int c = 0; c < 4; c++) g_Xe[(size_t)m * Ee + tx * 4 + c] = acc[r][c];
    }
}

// ---------------- Gx = Xe @ WihTpE + biasE ----------------
__global__ void __launch_bounds__(256) gx_kernel() {
    __shared__ float As[64][65];
    __shared__ float Bs[64][64];
    int tid = threadIdx.x;
    int tx = tid & 15, ty = tid >> 4;
    int m0 = blockIdx.x * 64;
    int n0 = blockIdx.y * 64;
    {
        int kk = tid & 63, mm = tid >> 6;
#pragma unroll
        for (int p = 0; p < 16; p++) {
            int m = mm + p * 4;
            As[kk][m] = g_Xe[(size_t)(m0 + m) * Ee + kk];
        }
    }
    {
        int nn = tid & 63, kk = tid >> 6;
#pragma unroll
        for (int p = 0; p < 16; p++) {
            int k = kk + p * 4;
            Bs[k][nn] = g_WihTpE[(size_t)k * G4 + n0 + nn];
        }
    }
    __syncthreads();
    float acc[4][4];
#pragma unroll
    for (int c = 0; c < 4; c++) {
        float b = g_biasE[n0 + tx * 4 + c];
#pragma unroll
        for (int r = 0; r < 4; r++) acc[r][c] = b;
    }
#pragma unroll
    for (int kk = 0; kk < 64; kk++) {
        float a[4], b[4];
#pragma unroll
        for (int r = 0; r < 4; r++) a[r] = As[kk][ty * 4 + r];
#pragma unroll
        for (int c = 0; c < 4; c++) b[c] = Bs[kk][tx * 4 + c];
#pragma unroll
        for (int r = 0; r < 4; r++)
#pragma unroll
            for (int c = 0; c < 4; c++) acc[r][c] += a[r] * b[c];
    }
#pragma unroll
    for (int r = 0; r < 4; r++) {
        int bt = m0 + ty * 4 + r;
        int b = bt >> 7, t = bt & 127;
        size_t base = ((size_t)t * Bb + b) * G4 + n0 + tx * 4;
#pragma unroll
        for (int c = 0; c < 4; c++) g_Gx[base + c] = acc[r][c];
    }
}

// ---------------- emb0 ----------------
__global__ void emb0_kernel(const float* __restrict__ x, const float* __restrict__ bd) {
    __shared__ float x0[Vv];
    int b = blockIdx.x, tid = threadIdx.x; // 64 threads
    for (int i = tid; i < Vv; i += 64) x0[i] = x[(size_t)b * Tt * Vv + i];
    __syncthreads();
    float acc = bd[tid];
    for (int v = 0; v < Vv; v++) acc += x0[v] * g_WdT[(size_t)v * Ee + tid];
    g_emb[b * Ee + tid] = acc;
}

// ---------------- init ----------------
__global__ void init_kernel(const int* __restrict__ xlens, float* __restrict__ out,
                            int write_extra) {
    int id = blockIdx.x * blockDim.x + threadIdx.x;
    if (id < Bb * Vv) {
        int b = id / Vv, v = id % Vv;
        out[(size_t)b * Tt * Vv + v] = 0.f;
    }
    if (write_extra && id < Bb) out[(size_t)Bb * Tt * Vv + id] = (float)xlens[id];
    if (id < Bb * Hh) { g_h[0][id] = 0.f; g_h[1][id] = 0.f; }
}

// ---------------- persistent recurrent kernel ----------------
__global__ void __launch_bounds__(NT, 1) rec_kernel(const int* __restrict__ xlens,
                                                    const float* __restrict__ bo,
                                                    float* __restrict__ out,
                                                    int write_extra) {
    extern __shared__ float dsm[];
    float* Ws = dsm;                       // [K][34]
    float* As = dsm + WS_FLOATS;           // [2][32][66]
    int*  sIdx = (int*)(dsm + SIDX_OFF);   // [64]
    // phase2 overlays on As region:
    float* hs = As;                        // [4][260]
    float* pv = As + 4 * 260;              // [4][8]
    int*   pi = (int*)(As + 4 * 260 + 32); // [4][8]

    const int tid = threadIdx.x, bx = blockIdx.x;
    const int tx = tid & 15, ty = tid >> 4;
    const int wid = tid >> 5, lane = tid & 31;
    const int m0 = (bx >> 5) * 64;
    const int n0 = (bx & 31) * 32;
    const int row0 = m0 + ty * 4;
    const int col0 = n0 + tx * 2;
    const bool evenT = ((tx & 1) == 0);
    const int junit = col0 >> 2;

    float c_reg[4] = {0.f, 0.f, 0.f, 0.f};
    float h_reg[4] = {0.f, 0.f, 0.f, 0.f};
    int lens[4];
#pragma unroll
    for (int r = 0; r < 4; r++) lens[r] = xlens[row0 + r];

    const unsigned FULL = 0xffffffffu;
    int par = 0;

    // ---- load encoder Whh tile into shared (K=256 x 32 cols) ----
    for (int i = tid; i < Hh * 32; i += NT) {
        int k = i >> 5, n = i & 31;
        Ws[k * WS_STRIDE + n] = g_WhhTpE[(size_t)k * G4 + n0 + n];
    }
    __syncthreads();

    const int skk = tid & 31, smm = tid >> 5;

    // ======================= encoder =======================
    for (int t = 0; t < Tt; ++t) {
        float acc[4][2];
        const float* gx = g_Gx + ((size_t)t * Bb) * G4;
#pragma unroll
        for (int r = 0; r < 4; r++) {
            acc[r][0] = __ldg(&gx[(size_t)(row0 + r) * G4 + col0]);
            acc[r][1] = __ldg(&gx[(size_t)(row0 + r) * G4 + col0 + 1]);
        }
        const float* hbuf = g_h[par];
        // stage ktile 0
        {
            const float* src = hbuf + (size_t)(m0 + smm) * Hh + skk;
            float* dst = As + skk * AS_STRIDE + smm;
#pragma unroll
            for (int p = 0; p < 8; p++) dst[p * 8] = ldcg(src + (size_t)(p * 8) * Hh);
        }
        __syncthreads();
        int buf = 0;
        for (int kt = 0; kt < NKT_E; ++kt) {
            if (kt + 1 < NKT_E) {
                int k0n = (kt + 1) * KT;
                const float* src = hbuf + (size_t)(m0 + smm) * Hh + k0n + skk;
                float* dst = As + (buf ^ 1) * AS_BUF + skk * AS_STRIDE + smm;
#pragma unroll
                for (int p = 0; p < 8; p++) dst[p * 8] = ldcg(src + (size_t)(p * 8) * Hh);
            }
            const float* Ab = As + buf * AS_BUF;
            const float* Wk = Ws + (kt * KT) * WS_STRIDE;
#pragma unroll
            for (int kk = 0; kk < KT; kk++) {
                float2 b2 = *(const float2*)&Wk[kk * WS_STRIDE + tx * 2];
                float2 alo = *(const float2*)&Ab[kk * AS_STRIDE + ty * 4];
                float2 ahi = *(const float2*)&Ab[kk * AS_STRIDE + ty * 4 + 2];
                acc[0][0] += alo.x * b2.x; acc[0][1] += alo.x * b2.y;
                acc[1][0] += alo.y * b2.x; acc[1][1] += alo.y * b2.y;
                acc[2][0] += ahi.x * b2.x; acc[2][1] += ahi.x * b2.y;
                acc[3][0] += ahi.y * b2.x; acc[3][1] += ahi.y * b2.y;
            }
            __syncthreads();
            buf ^= 1;
        }
#pragma unroll
        for (int r = 0; r < 4; r++) {
            float gg = __shfl_down_sync(FULL, acc[r][0], 1);
            float go = __shfl_down_sync(FULL, acc[r][1], 1);
            if (evenT) {
                float i_ = sigm(acc[r][0]), f_ = sigm(acc[r][1]);
                float gv = tanhf(gg), o_ = sigm(go);
                float cn = f_ * c_reg[r] + i_ * gv;
                float hn = o_ * tanhf(cn);
                bool msk = (t < lens[r]);
                c_reg[r] = msk ? cn : c_reg[r];
                float hv = msk ? hn : h_reg[r];
                h_reg[r] = hv;
                stcg(&g_h[par ^ 1][(size_t)(row0 + r) * Hh + junit], hv);
            }
        }
        grid_bar();
        par ^= 1;
    }

    if (write_extra && evenT) {
#pragma unroll
        for (int r = 0; r < 4; r++)
            out[(size_t)Bb * Tt * Vv + Bb + (size_t)(row0 + r) * Hh + junit] = h_reg[r];
    }

    // ---- load decoder stacked weight tile (K=320 x 32 cols) ----
    for (int i = tid; i < KD * 32; i += NT) {
        int k = i >> 5, n = i & 31;
        Ws[k * WS_STRIDE + n] = g_WsTpD[(size_t)k * G4 + n0 + n];
    }
    float biasD0 = g_biasD[col0], biasD1 = g_biasD[col0 + 1];
    // phase2 constants
    const int vh = bx & 1, bg = bx >> 1;
    const int r0p2 = bg * 4;
    const int colp2 = vh * 256 + tid;
    const float bo_reg = bo[colp2];
    __syncthreads();

    // ======================= decoder =======================
    for (int s = 0; s < Tt - 1; ++s) {
        // combined argmax indices for this block's 64 rows
        if (s > 0 && tid < 64) {
            int row = m0 + tid;
            float v0 = ldcg(&g_av[row]), v1 = ldcg(&g_av[Bb + row]);
            int i0 = ldcg_i(&g_ai[row]), i1 = ldcg_i(&g_ai[Bb + row]);
            sIdx[tid] = (v1 > v0) ? i1 : i0;
        }
        __syncthreads();

        float acc[4][2];
#pragma unroll
        for (int r = 0; r < 4; r++) { acc[r][0] = biasD0; acc[r][1] = biasD1; }
        const float* hbuf = g_h[par];

        // stage ktile 0 (emb region)
        {
            float* dst = As + skk * AS_STRIDE + smm;
            if (s == 0) {
                const float* src = g_emb + (size_t)(m0 + smm) * Ee + skk;
#pragma unroll
                for (int p = 0; p < 8; p++) dst[p * 8] = ldcg(src + (size_t)(p * 8) * Ee);
            } else {
#pragma unroll
                for (int p = 0; p < 8; p++) {
                    int idx = sIdx[smm + p * 8];
                    dst[p * 8] = __ldg(&g_WdTb[(size_t)idx * Ee + skk]);
                }
            }
        }
        __syncthreads();
        int buf = 0;
        for (int kt = 0; kt < NKT_D; ++kt) {
            if (kt + 1 < NKT_D) {
                int k0n = (kt + 1) * KT;
                float* dst = As + (buf ^ 1) * AS_BUF + skk * AS_STRIDE + smm;
                if (k0n < Ee) { // ktile 1: emb part
                    if (s == 0) {
                        const float* src = g_emb + (size_t)(m0 + smm) * Ee + k0n + skk;
#pragma unroll
                        for (int p = 0; p < 8; p++) dst[p * 8] = ldcg(src + (size_t)(p * 8) * Ee);
                    } else {
#pragma unroll
                        for (int p = 0; p < 8; p++) {
                            int idx = sIdx[smm + p * 8];
                            dst[p * 8] = __ldg(&g_WdTb[(size_t)idx * Ee + k0n + skk]);
                        }
                    }
                } else {
                    const float* src = hbuf + (size_t)(m0 + smm) * Hh + (k0n - Ee) + skk;
#pragma unroll
                    for (int p = 0; p < 8; p++) dst[p * 8] = ldcg(src + (size_t)(p * 8) * Hh);
                }
            }
            const float* Ab = As + buf * AS_BUF;
            const float* Wk = Ws + (kt * KT) * WS_STRIDE;
#pragma unroll
            for (int kk = 0; kk < KT; kk++) {
                float2 b2 = *(const float2*)&Wk[kk * WS_STRIDE + tx * 2];
                float2 alo = *(const float2*)&Ab[kk * AS_STRIDE + ty * 4];
                float2 ahi = *(const float2*)&Ab[kk * AS_STRIDE + ty * 4 + 2];
                acc[0][0] += alo.x * b2.x; acc[0][1] += alo.x * b2.y;
                acc[1][0] += alo.y * b2.x; acc[1][1] += alo.y * b2.y;
                acc[2][0] += ahi.x * b2.x; acc[2][1] += ahi.x * b2.y;
                acc[3][0] += ahi.y * b2.x; acc[3][1] += ahi.y * b2.y;
            }
            __syncthreads();
            buf ^= 1;
        }
#pragma unroll
        for (int r = 0; r < 4; r++) {
            float gg = __shfl_down_sync(FULL, acc[r][0], 1);
            float go = __shfl_down_sync(FULL, acc[r][1], 1);
            if (evenT) {
                float i_ = sigm(acc[r][0]), f_ = sigm(acc[r][1]);
                float gv = tanhf(gg), o_ = sigm(go);
                float cn = f_ * c_reg[r] + i_ * gv;
                float hn = o_ * tanhf(cn);
                c_reg[r] = cn;
                h_reg[r] = hn;
                stcg(&g_h[par ^ 1][(size_t)(row0 + r) * Hh + junit], hn);
            }
        }
        grid_bar();
        par ^= 1;

        // ---- phase2: logits 4 rows x 256 cols (all 128 blocks) ----
        {
            const float* hb = g_h[par];
#pragma unroll
            for (int r = 0; r < 4; r++)
                hs[r * 260 + tid] = ldcg(&hb[(size_t)(r0p2 + r) * Hh + tid]);
            __syncthreads();
            float acc2[4] = {bo_reg, bo_reg, bo_reg, bo_reg};
            for (int k0 = 0; k0 < Hh; k0 += 8) {
                float w[8];
#pragma unroll
                for (int u = 0; u < 8; u++)
                    w[u] = __ldg(&g_WoT[(size_t)(k0 + u) * Vv + colp2]);
#pragma unroll
                for (int u = 0; u < 8; u++) {
#pragma unroll
                    for (int r = 0; r < 4; r++)
                        acc2[r] += hs[r * 260 + k0 + u] * w[u];
                }
            }
            // write y
#pragma unroll
            for (int r = 0; r < 4; r++)
                out[(size_t)(r0p2 + r) * Tt * Vv + (size_t)(s + 1) * Vv + colp2] = acc2[r];
            // warp-level argmax
            float bv[4]; int bi[4];
#pragma unroll
            for (int r = 0; r < 4; r++) { bv[r] = acc2[r]; bi[r] = colp2; }
#pragma unroll
            for (int off = 16; off > 0; off >>= 1) {
#pragma unroll
                for (int r = 0; r < 4; r++) {
                    float ov = __shfl_down_sync(FULL, bv[r], off);
                    int oi = __shfl_down_sync(FULL, bi[r], off);
                    if (ov > bv[r] || (ov == bv[r] && oi < bi[r])) { bv[r] = ov; bi[r] = oi; }
                }
            }
            if (lane == 0) {
#pragma unroll
                for (int r = 0; r < 4; r++) { pv[r * 8 + wid] = bv[r]; pi[r * 8 + wid] = bi[r]; }
            }
            __syncthreads();
            if (wid == 0 && lane < 8) {
#pragma unroll
                for (int r = 0; r < 4; r++) {
                    float v = pv[r * 8 + lane]; int i = pi[r * 8 + lane];
#pragma unroll
                    for (int off = 4; off > 0; off >>= 1) {
                        float ov = __shfl_down_sync(0xffu, v, off, 8);
                        int oi = __shfl_down_sync(0xffu, i, off, 8);
                        if (ov > v || (ov == v && oi < i)) { v = ov; i = oi; }
                    }
                    if (lane == 0) {
                        stcg(&g_av[vh * Bb + r0p2 + r], v);
                        stcg_i(&g_ai[vh * Bb + r0p2 + r], i);
                    }
                }
            }
        }
        grid_bar();
    }
}

// ---------------- launch ----------------
extern "C" void kernel_launch(void* const* d_in, const int* in_sizes, int n_in,
                              void* d_out, int out_size) {
    (void)in_sizes; (void)n_in;
    const float* x     = (const float*)d_in[0];
    const int*   xlens = (const int*)  d_in[1];
    const float* We    = (const float*)d_in[2];
    const float* be    = (const float*)d_in[3];
    const float* Wih_e = (const float*)d_in[4];
    const float* Whh_e = (const float*)d_in[5];
    const float* bih_e = (const float*)d_in[6];
    const float* bhh_e = (const float*)d_in[7];
    const float* Wd    = (const float*)d_in[8];
    const float* bd    = (const float*)d_in[9];
    const float* Wih_d = (const float*)d_in[10];
    const float* Whh_d = (const float*)d_in[11];
    const float* bih_d = (const float*)d_in[12];
    const float* bhh_d = (const float*)d_in[13];
    const float* Wo    = (const float*)d_in[14];
    const float* bo    = (const float*)d_in[15];
    float* out = (float*)d_out;

    int write_extra = (out_size >= Bb * Tt * Vv + Bb + Bb * Hh) ? 1 : 0;

    static int smem_set = 0;
    if (!smem_set) {
        cudaFuncSetAttribute(rec_kernel, cudaFuncAttributeMaxDynamicSharedMemorySize, DSM_BYTES);
        smem_set = 1;
    }

    pack_kernel<<<1024, 256>>>(We, Wih_e, Whh_e, bih_e, bhh_e,
                               Wd, bd, Wih_d, Whh_d, bih_d, bhh_d, Wo);
    xe_kernel<<<512, 256>>>(x, be);
    gx_kernel<<<dim3(512, 16), 256>>>();
    emb0_kernel<<<Bb, 64>>>(x, bd);
    init_kernel<<<512, 256>>>(xlens, out, write_extra);
    rec_kernel<<<NB, NT, DSM_BYTES>>>(xlens, bo, out, write_extra);
}